// round 10
// baseline (speedup 1.0000x reference)
#include <cuda_runtime.h>
#include <cstdint>

// Correlation1D via warp-level tf32 mma.sync band-GEMM, cp.async 3-stage pipeline.
// out[b,d,h,w] = (1/256) * sum_c in1[b,c,h,w] * in2[b,c,h,w+d-40], d in [0,81)
// Per CTA (b,h): D[w, sj] = sum_c in1[c,w] * in2[c, sj-40], sj = w+d in [0,272).
// 12 warps: warp mt owns w0=16*mt, n-tiles sj in [w0, w0+96) -> 12 tiles of 8.
// f32 staged raw via cp.async (zero-fill OOB). RNA->tf32 conversion happens ONCE
// per staged word, in place, one pipeline step ahead of consumption (overlapped
// with the previous chunk's MMAs). Empty tail commits keep the wait_group invariant.

#define BB 8
#define CC 256
#define HH 96
#define WW 192
#define DD 81
#define HW (HH*WW)
#define CHW ((size_t)CC*(size_t)HW)

#define NTHR 384
#define KC 16                 // k-rows per chunk
#define NKC (CC/KC)           // 16 chunks
#define NSTG 3                // pipeline stages
#define SAW 200               // A row stride (words): conflict-free
#define SBW 280               // B row stride (words): conflict-free
#define SB_OFF (KC*SAW)       // 3200 words
#define STG_W (KC*SAW + KC*SBW)     // 7680 words per stage (= 1920 uint4)
#define SMEM_BYTES (NSTG*STG_W*4)   // 92160

__device__ __forceinline__ void cp16(uint32_t daddr, const float* src, uint32_t sz) {
    asm volatile("cp.async.cg.shared.global [%0], [%1], 16, %2;"
                 :: "r"(daddr), "l"(src), "r"(sz));
}

__device__ __forceinline__ uint32_t f2tf32(uint32_t raw) {
    uint32_t u;
    asm("cvt.rna.tf32.f32 %0, %1;" : "=r"(u) : "f"(__uint_as_float(raw)));
    return u;
}

__device__ __forceinline__ void mma_tf32(float (&d)[4], const uint32_t (&a)[4],
                                         uint32_t b0, uint32_t b1) {
    asm volatile(
        "mma.sync.aligned.m16n8k8.row.col.f32.tf32.tf32.f32 "
        "{%0,%1,%2,%3}, {%4,%5,%6,%7}, {%8,%9}, {%0,%1,%2,%3};"
        : "+f"(d[0]), "+f"(d[1]), "+f"(d[2]), "+f"(d[3])
        : "r"(a[0]), "r"(a[1]), "r"(a[2]), "r"(a[3]), "r"(b0), "r"(b1));
}

extern __shared__ uint32_t smem[];

__global__ __launch_bounds__(NTHR, 2)
void corr_hmma8(const float* __restrict__ in1, const float* __restrict__ in2,
                float* __restrict__ out) {
    const int h    = blockIdx.x;
    const int b    = blockIdx.y;
    const int tid  = threadIdx.x;
    const int wid  = tid >> 5;
    const int lane = tid & 31;
    const int g    = lane >> 2;
    const int l4   = lane & 3;
    const int w0   = wid * 16;

    const float* p1 = in1 + (size_t)b * CHW + (size_t)h * WW;
    const float* p2 = in2 + (size_t)b * CHW + (size_t)h * WW;
    float* pout = out + (size_t)b * DD * HW + (size_t)h * WW;

    uint32_t smem_u32;
    {
        uint32_t a;
        asm("{ .reg .u64 t; cvta.to.shared.u64 t, %1; cvt.u32.u64 %0, t; }"
            : "=r"(a) : "l"((const void*)smem));
        smem_u32 = a;
    }

    // per-thread cp.async assignments (2 A ops + up to 3 B ops per thread)
    const int a0r = tid / 48,         a0s = tid % 48;
    const int a1r = (tid + 384) / 48, a1s = (tid + 384) % 48;
    const int b0r = tid / 68,         b0j = tid % 68;
    const int b1r = (tid + 384) / 68, b1j = (tid + 384) % 68;
    const int b2r = (tid + 768) / 68, b2j = (tid + 768) % 68;
    const bool hasB2 = (tid + 768 < KC * 68);
    const uint32_t b0sz = (b0j >= 10 && b0j < 58) ? 16u : 0u;
    const uint32_t b1sz = (b1j >= 10 && b1j < 58) ? 16u : 0u;
    const uint32_t b2sz = (b2j >= 10 && b2j < 58) ? 16u : 0u;

    float acc[12][4];
#pragma unroll
    for (int nt = 0; nt < 12; nt++)
#pragma unroll
        for (int ci = 0; ci < 4; ci++) acc[nt][ci] = 0.f;

    auto issue = [&](int kc, int st) {
        if (kc < NKC) {
            const uint32_t sb = smem_u32 + (uint32_t)st * STG_W * 4;
            const size_t ko = (size_t)kc * KC * HW;
            cp16(sb + (a0r * SAW + a0s * 4) * 4, p1 + ko + (size_t)a0r * HW + a0s * 4, 16u);
            cp16(sb + (a1r * SAW + a1s * 4) * 4, p1 + ko + (size_t)a1r * HW + a1s * 4, 16u);
            cp16(sb + (SB_OFF + b0r * SBW + b0j * 4) * 4, p2 + ko + (size_t)b0r * HW + b0j * 4 - 40, b0sz);
            cp16(sb + (SB_OFF + b1r * SBW + b1j * 4) * 4, p2 + ko + (size_t)b1r * HW + b1j * 4 - 40, b1sz);
            if (hasB2)
                cp16(sb + (SB_OFF + b2r * SBW + b2j * 4) * 4, p2 + ko + (size_t)b2r * HW + b2j * 4 - 40, b2sz);
        }
        asm volatile("cp.async.commit_group;" ::: "memory");  // always commit (tail invariant)
    };

    // in-place RNA->tf32 conversion of one whole stage (5 uint4 per thread)
    auto cvt_stage = [&](int st) {
        uint4* sc = reinterpret_cast<uint4*>(smem + st * STG_W);
#pragma unroll
        for (int i = 0; i < 5; i++) {
            uint4 v = sc[tid + i * NTHR];
            v.x = f2tf32(v.x); v.y = f2tf32(v.y);
            v.z = f2tf32(v.z); v.w = f2tf32(v.w);
            sc[tid + i * NTHR] = v;
        }
    };

    issue(0, 0);
    issue(1, 1);
    issue(2, 2);

    // prologue: chunk 0 landed -> convert it
    asm volatile("cp.async.wait_group 2;" ::: "memory");
    __syncthreads();
    cvt_stage(0);

    int st = 0;   // stage of chunk kc
    for (int kc = 0; kc < NKC; kc++) {
        // chunks <= kc+1 have landed (3 prologue commits + one per iter, wait<=1 pending)
        asm volatile("cp.async.wait_group 1;" ::: "memory");
        __syncthreads();   // also publishes cvt_stage(kc) from previous iteration

        // convert next chunk (different stage) -- overlapped with this chunk's MMAs
        const int st1 = (st + 1 == NSTG) ? 0 : st + 1;
        if (kc + 1 < NKC) cvt_stage(st1);

        const uint32_t* sb = smem + st * STG_W;
#pragma unroll
        for (int ks = 0; ks < KC; ks += 8) {
            uint32_t a[4];
            a[0] = sb[(ks + l4) * SAW + w0 + g];
            a[1] = sb[(ks + l4) * SAW + w0 + g + 8];
            a[2] = sb[(ks + l4 + 4) * SAW + w0 + g];
            a[3] = sb[(ks + l4 + 4) * SAW + w0 + g + 8];
#pragma unroll
            for (int nt = 0; nt < 12; nt++) {
                const int bc = w0 + 8 * nt + g;
                const uint32_t bb0 = sb[SB_OFF + (ks + l4) * SBW + bc];
                const uint32_t bb1 = sb[SB_OFF + (ks + l4 + 4) * SBW + bc];
                mma_tf32(acc[nt], a, bb0, bb1);
            }
        }
        __syncthreads();          // all reads of stage st done before re-filling it
        issue(kc + NSTG, st);     // refill the stage just consumed
        st = st1;
    }

    // ---- epilogue: diagonal extract d = sj - wp, coalesced float4 stores ----
    float* buf = reinterpret_cast<float*>(smem);   // [32][SAW] floats (aliases stage 0)
#pragma unroll
    for (int chunk = 0; chunk < 3; chunk++) {
        const int d0 = chunk * 32;
        if (chunk) __syncthreads();
#pragma unroll
        for (int nt = 0; nt < 12; nt++) {
#pragma unroll
            for (int ci = 0; ci < 4; ci++) {
                const int wp = w0 + g + ((ci & 2) ? 8 : 0);
                const int sj = w0 + 8 * nt + 2 * l4 + (ci & 1);
                const int d  = sj - wp;
                if (d >= d0 && d < d0 + 32 && d < DD)
                    buf[(d - d0) * SAW + wp] = acc[nt][ci] * (1.0f / 256.0f);
            }
        }
        __syncthreads();
        const int dmax = (DD - d0 < 32) ? (DD - d0) : 32;
        for (int i = tid; i < dmax * 48; i += NTHR) {
            const int dd = i / 48;
            const int v  = i - dd * 48;
            *reinterpret_cast<float4*>(pout + (size_t)(d0 + dd) * HW + v * 4) =
                *reinterpret_cast<float4*>(&buf[dd * SAW + v * 4]);
        }
    }
}

extern "C" void kernel_launch(void* const* d_in, const int* in_sizes, int n_in,
                              void* d_out, int out_size) {
    const float* in1 = (const float*)d_in[0];
    const float* in2 = (const float*)d_in[1];
    float* out = (float*)d_out;

    cudaFuncSetAttribute(corr_hmma8, cudaFuncAttributeMaxDynamicSharedMemorySize, SMEM_BYTES);
    dim3 grid(HH, BB);   // 768 CTAs x 384 threads
    corr_hmma8<<<grid, NTHR, SMEM_BYTES>>>(in1, in2, out);
}

// round 11
// speedup vs baseline: 1.2871x; 1.2871x over previous
#include <cuda_runtime.h>
#include <cstdint>

// Correlation1D via warp-level tf32 mma.sync band-GEMM, cp.async 3-stage pipeline,
// m-tile-PAIRED warps (B-fragment reuse).
// out[b,d,h,w] = (1/256) * sum_c in1[b,c,h,w] * in2[b,c,h,w+d-40], d in [0,81)
// Per CTA (b,h): D[w, sj] = sum_c in1[c,w] * in2[c, sj-40], sj = w+d in [0,272).
// 6 warps: warp wid owns m-tiles {w0, w0+16}, w0 = 32*wid; shared B n-tiles
// ntg = 0..13 (sj in [w0, w0+112)); m-tile0 uses ntg 0..11, m-tile1 uses 2..13.
// f32 staged raw via cp.async (zero-fill OOB); RNA->tf32 applied to fragments after LDS.
// Always-commit empty tail groups keep the wait_group counting invariant.

#define BB 8
#define CC 256
#define HH 96
#define WW 192
#define DD 81
#define HW (HH*WW)
#define CHW ((size_t)CC*(size_t)HW)

#define NTHR 192
#define KC 16                 // k-rows per chunk
#define NKC (CC/KC)           // 16 chunks
#define NSTG 3                // pipeline stages
#define SAW 200               // A row stride (words): conflict-free
#define SBW 280               // B row stride (words): conflict-free
#define SB_OFF (KC*SAW)       // 3200 words
#define STG_W (KC*SAW + KC*SBW)     // 7680 words per stage
#define SMEM_BYTES (NSTG*STG_W*4)   // 92160

__device__ __forceinline__ void cp16(uint32_t daddr, const float* src, uint32_t sz) {
    asm volatile("cp.async.cg.shared.global [%0], [%1], 16, %2;"
                 :: "r"(daddr), "l"(src), "r"(sz));
}

__device__ __forceinline__ uint32_t f2tf32(uint32_t raw) {
    uint32_t u;
    asm("cvt.rna.tf32.f32 %0, %1;" : "=r"(u) : "f"(__uint_as_float(raw)));
    return u;
}

__device__ __forceinline__ void mma_tf32(float (&d)[4], const uint32_t (&a)[4],
                                         uint32_t b0, uint32_t b1) {
    asm volatile(
        "mma.sync.aligned.m16n8k8.row.col.f32.tf32.tf32.f32 "
        "{%0,%1,%2,%3}, {%4,%5,%6,%7}, {%8,%9}, {%0,%1,%2,%3};"
        : "+f"(d[0]), "+f"(d[1]), "+f"(d[2]), "+f"(d[3])
        : "r"(a[0]), "r"(a[1]), "r"(a[2]), "r"(a[3]), "r"(b0), "r"(b1));
}

extern __shared__ uint32_t smem[];

__global__ __launch_bounds__(NTHR, 2)
void corr_hmma9(const float* __restrict__ in1, const float* __restrict__ in2,
                float* __restrict__ out) {
    const int h    = blockIdx.x;
    const int b    = blockIdx.y;
    const int tid  = threadIdx.x;
    const int wid  = tid >> 5;
    const int lane = tid & 31;
    const int g    = lane >> 2;
    const int l4   = lane & 3;
    const int w0   = wid * 32;   // warp owns m-tiles at w0 and w0+16

    const float* p1 = in1 + (size_t)b * CHW + (size_t)h * WW;
    const float* p2 = in2 + (size_t)b * CHW + (size_t)h * WW;
    float* pout = out + (size_t)b * DD * HW + (size_t)h * WW;

    uint32_t smem_u32;
    {
        uint32_t a;
        asm("{ .reg .u64 t; cvta.to.shared.u64 t, %1; cvt.u32.u64 %0, t; }"
            : "=r"(a) : "l"((const void*)smem));
        smem_u32 = a;
    }

    // per-thread cp.async assignments: A 4 ops (16x48 float4), B 6 ops (16x68 float4)
    int  ar[4], as_[4];
#pragma unroll
    for (int k = 0; k < 4; k++) { const int i = tid + k * NTHR; ar[k] = i / 48; as_[k] = i % 48; }
    int  br[6], bj[6];
    uint32_t bsz[6];
    bool bact[6];
#pragma unroll
    for (int k = 0; k < 6; k++) {
        const int i = tid + k * NTHR;
        bact[k] = (i < KC * 68);
        br[k] = i / 68; bj[k] = i % 68;
        bsz[k] = (bj[k] >= 10 && bj[k] < 58) ? 16u : 0u;
    }

    float acc[2][12][4];
#pragma unroll
    for (int mt = 0; mt < 2; mt++)
#pragma unroll
        for (int nt = 0; nt < 12; nt++)
#pragma unroll
            for (int ci = 0; ci < 4; ci++) acc[mt][nt][ci] = 0.f;

    auto issue = [&](int kc, int st) {
        if (kc < NKC) {
            const uint32_t sb = smem_u32 + (uint32_t)st * STG_W * 4;
            const size_t ko = (size_t)kc * KC * HW;
#pragma unroll
            for (int k = 0; k < 4; k++)
                cp16(sb + (ar[k] * SAW + as_[k] * 4) * 4,
                     p1 + ko + (size_t)ar[k] * HW + as_[k] * 4, 16u);
#pragma unroll
            for (int k = 0; k < 6; k++)
                if (bact[k])
                    cp16(sb + (SB_OFF + br[k] * SBW + bj[k] * 4) * 4,
                         p2 + ko + (size_t)br[k] * HW + bj[k] * 4 - 40, bsz[k]);
        }
        asm volatile("cp.async.commit_group;" ::: "memory");  // always commit (tail invariant)
    };

    issue(0, 0);
    issue(1, 1);
    issue(2, 2);

    int st = 0;   // stage of chunk kc
    for (int kc = 0; kc < NKC; kc++) {
        asm volatile("cp.async.wait_group 2;" ::: "memory");
        __syncthreads();
        const uint32_t* sb = smem + st * STG_W;

#pragma unroll
        for (int ks = 0; ks < KC; ks += 8) {
            uint32_t a0[4], a1[4];
            a0[0] = f2tf32(sb[(ks + l4) * SAW + w0 + g]);
            a0[1] = f2tf32(sb[(ks + l4) * SAW + w0 + g + 8]);
            a0[2] = f2tf32(sb[(ks + l4 + 4) * SAW + w0 + g]);
            a0[3] = f2tf32(sb[(ks + l4 + 4) * SAW + w0 + g + 8]);
            a1[0] = f2tf32(sb[(ks + l4) * SAW + w0 + 16 + g]);
            a1[1] = f2tf32(sb[(ks + l4) * SAW + w0 + 16 + g + 8]);
            a1[2] = f2tf32(sb[(ks + l4 + 4) * SAW + w0 + 16 + g]);
            a1[3] = f2tf32(sb[(ks + l4 + 4) * SAW + w0 + 16 + g + 8]);
#pragma unroll
            for (int nt = 0; nt < 14; nt++) {
                const int bc = w0 + 8 * nt + g;
                const uint32_t bb0 = f2tf32(sb[SB_OFF + (ks + l4) * SBW + bc]);
                const uint32_t bb1 = f2tf32(sb[SB_OFF + (ks + l4 + 4) * SBW + bc]);
                if (nt < 12) mma_tf32(acc[0][nt], a0, bb0, bb1);
                if (nt >= 2) mma_tf32(acc[1][nt - 2], a1, bb0, bb1);
            }
        }
        __syncthreads();          // all reads of stage st done before re-filling it
        issue(kc + NSTG, st);     // refill the stage just consumed
        st = (st + 1 == NSTG) ? 0 : st + 1;
    }

    // ---- epilogue: diagonal extract d = sj - wp, coalesced float4 stores ----
    float* buf = reinterpret_cast<float*>(smem);   // [32][SAW] floats (aliases stage 0)
#pragma unroll
    for (int chunk = 0; chunk < 3; chunk++) {
        const int d0 = chunk * 32;
        if (chunk) __syncthreads();
#pragma unroll
        for (int mt = 0; mt < 2; mt++) {
#pragma unroll
            for (int nt = 0; nt < 12; nt++) {
                const int ntg = nt + 2 * mt;
#pragma unroll
                for (int ci = 0; ci < 4; ci++) {
                    const int wp = w0 + 16 * mt + g + ((ci & 2) ? 8 : 0);
                    const int sj = w0 + 8 * ntg + 2 * l4 + (ci & 1);
                    const int d  = sj - wp;
                    if (d >= d0 && d < d0 + 32 && d < DD)
                        buf[(d - d0) * SAW + wp] = acc[mt][nt][ci] * (1.0f / 256.0f);
                }
            }
        }
        __syncthreads();
        const int dmax = (DD - d0 < 32) ? (DD - d0) : 32;
        for (int i = tid; i < dmax * 48; i += NTHR) {
            const int dd = i / 48;
            const int v  = i - dd * 48;
            *reinterpret_cast<float4*>(pout + (size_t)(d0 + dd) * HW + v * 4) =
                *reinterpret_cast<float4*>(&buf[dd * SAW + v * 4]);
        }
    }
}

extern "C" void kernel_launch(void* const* d_in, const int* in_sizes, int n_in,
                              void* d_out, int out_size) {
    const float* in1 = (const float*)d_in[0];
    const float* in2 = (const float*)d_in[1];
    float* out = (float*)d_out;

    cudaFuncSetAttribute(corr_hmma9, cudaFuncAttributeMaxDynamicSharedMemorySize, SMEM_BYTES);
    dim3 grid(HH, BB);   // 768 CTAs x 192 threads
    corr_hmma9<<<grid, NTHR, SMEM_BYTES>>>(in1, in2, out);
}

// round 12
// speedup vs baseline: 1.3186x; 1.0245x over previous
#include <cuda_runtime.h>
#include <cstdint>

// Correlation1D via warp-level tf32 mma.sync band-GEMM.
// 6-stage cp.async pipeline with KC=8 chunks; loads issued BEFORE compute each
// iteration (refill target was consumed one full iteration ago), one barrier
// per chunk. m-tile-paired warps for B-fragment reuse.
// out[b,d,h,w] = (1/256) * sum_c in1[b,c,h,w] * in2[b,c,h,w+d-40], d in [0,81)
// Per CTA (b,h): D[w, sj] = sum_c in1[c,w] * in2[c, sj-40], sj = w+d in [0,272).
// 6 warps: warp wid owns m-tiles {w0, w0+16}, w0 = 32*wid; shared B n-tiles
// ntg = 0..13; m-tile0 uses ntg 0..11, m-tile1 uses 2..13.
// f32 staged raw via cp.async (zero-fill OOB); RNA->tf32 applied after LDS.
// Always-commit empty tail groups keep the wait_group counting invariant.

#define BB 8
#define CC 256
#define HH 96
#define WW 192
#define DD 81
#define HW (HH*WW)
#define CHW ((size_t)CC*(size_t)HW)

#define NTHR 192
#define KC 8                  // k-rows per chunk
#define NKC (CC/KC)           // 32 chunks
#define NSTG 6                // pipeline stages
#define SAW 200               // A row stride (words): conflict-free
#define SBW 280               // B row stride (words): conflict-free
#define SB_OFF (KC*SAW)       // 1600 words
#define STG_W (KC*SAW + KC*SBW)     // 3840 words per stage
#define SMEM_BYTES (NSTG*STG_W*4)   // 92160 (same as 3x16-row stages)

__device__ __forceinline__ void cp16(uint32_t daddr, const float* src, uint32_t sz) {
    asm volatile("cp.async.cg.shared.global [%0], [%1], 16, %2;"
                 :: "r"(daddr), "l"(src), "r"(sz));
}

__device__ __forceinline__ uint32_t f2tf32(uint32_t raw) {
    uint32_t u;
    asm("cvt.rna.tf32.f32 %0, %1;" : "=r"(u) : "f"(__uint_as_float(raw)));
    return u;
}

__device__ __forceinline__ void mma_tf32(float (&d)[4], const uint32_t (&a)[4],
                                         uint32_t b0, uint32_t b1) {
    asm volatile(
        "mma.sync.aligned.m16n8k8.row.col.f32.tf32.tf32.f32 "
        "{%0,%1,%2,%3}, {%4,%5,%6,%7}, {%8,%9}, {%0,%1,%2,%3};"
        : "+f"(d[0]), "+f"(d[1]), "+f"(d[2]), "+f"(d[3])
        : "r"(a[0]), "r"(a[1]), "r"(a[2]), "r"(a[3]), "r"(b0), "r"(b1));
}

extern __shared__ uint32_t smem[];

__global__ __launch_bounds__(NTHR, 2)
void corr_hmma10(const float* __restrict__ in1, const float* __restrict__ in2,
                 float* __restrict__ out) {
    const int h    = blockIdx.x;
    const int b    = blockIdx.y;
    const int tid  = threadIdx.x;
    const int wid  = tid >> 5;
    const int lane = tid & 31;
    const int g    = lane >> 2;
    const int l4   = lane & 3;
    const int w0   = wid * 32;   // warp owns m-tiles at w0 and w0+16

    const float* p1 = in1 + (size_t)b * CHW + (size_t)h * WW;
    const float* p2 = in2 + (size_t)b * CHW + (size_t)h * WW;
    float* pout = out + (size_t)b * DD * HW + (size_t)h * WW;

    uint32_t smem_u32;
    {
        uint32_t a;
        asm("{ .reg .u64 t; cvta.to.shared.u64 t, %1; cvt.u32.u64 %0, t; }"
            : "=r"(a) : "l"((const void*)smem));
        smem_u32 = a;
    }

    // per-thread cp.async assignments: A 2 ops (8x48 float4), B 3 ops (8x68 float4)
    int ar[2], as_[2];
#pragma unroll
    for (int k = 0; k < 2; k++) { const int i = tid + k * NTHR; ar[k] = i / 48; as_[k] = i % 48; }
    int br[3], bj[3];
    uint32_t bsz[3];
    bool bact[3];
#pragma unroll
    for (int k = 0; k < 3; k++) {
        const int i = tid + k * NTHR;
        bact[k] = (i < KC * 68);
        br[k] = i / 68; bj[k] = i % 68;
        bsz[k] = (bj[k] >= 10 && bj[k] < 58) ? 16u : 0u;
    }

    float acc[2][12][4];
#pragma unroll
    for (int mt = 0; mt < 2; mt++)
#pragma unroll
        for (int nt = 0; nt < 12; nt++)
#pragma unroll
            for (int ci = 0; ci < 4; ci++) acc[mt][nt][ci] = 0.f;

    auto issue = [&](int kc) {
        if (kc < NKC) {
            const uint32_t sb = smem_u32 + (uint32_t)(kc % NSTG) * STG_W * 4;
            const size_t ko = (size_t)kc * KC * HW;
#pragma unroll
            for (int k = 0; k < 2; k++)
                cp16(sb + (ar[k] * SAW + as_[k] * 4) * 4,
                     p1 + ko + (size_t)ar[k] * HW + as_[k] * 4, 16u);
#pragma unroll
            for (int k = 0; k < 3; k++)
                if (bact[k])
                    cp16(sb + (SB_OFF + br[k] * SBW + bj[k] * 4) * 4,
                         p2 + ko + (size_t)br[k] * HW + bj[k] * 4 - 40, bsz[k]);
        }
        asm volatile("cp.async.commit_group;" ::: "memory");  // always commit (tail invariant)
    };

    // prologue: fill 5 of 6 stages
#pragma unroll
    for (int k = 0; k < NSTG - 1; k++) issue(k);

    for (int kc = 0; kc < NKC; kc++) {
        // commits so far = 5 + kc; wait<=4 pending -> chunks 0..kc landed
        asm volatile("cp.async.wait_group 4;" ::: "memory");
        __syncthreads();           // publish chunk kc; prove stage(kc-1) readers done
        issue(kc + NSTG - 1);      // refill stage (kc+5)%6 == stage(kc-1): free

        const uint32_t* sb = smem + (kc % NSTG) * STG_W;
        // single k8 step (KC=8)
        uint32_t a0[4], a1[4];
        a0[0] = f2tf32(sb[l4 * SAW + w0 + g]);
        a0[1] = f2tf32(sb[l4 * SAW + w0 + g + 8]);
        a0[2] = f2tf32(sb[(l4 + 4) * SAW + w0 + g]);
        a0[3] = f2tf32(sb[(l4 + 4) * SAW + w0 + g + 8]);
        a1[0] = f2tf32(sb[l4 * SAW + w0 + 16 + g]);
        a1[1] = f2tf32(sb[l4 * SAW + w0 + 16 + g + 8]);
        a1[2] = f2tf32(sb[(l4 + 4) * SAW + w0 + 16 + g]);
        a1[3] = f2tf32(sb[(l4 + 4) * SAW + w0 + 16 + g + 8]);
#pragma unroll
        for (int nt = 0; nt < 14; nt++) {
            const int bc = w0 + 8 * nt + g;
            const uint32_t bb0 = f2tf32(sb[SB_OFF + l4 * SBW + bc]);
            const uint32_t bb1 = f2tf32(sb[SB_OFF + (l4 + 4) * SBW + bc]);
            if (nt < 12) mma_tf32(acc[0][nt], a0, bb0, bb1);
            if (nt >= 2) mma_tf32(acc[1][nt - 2], a1, bb0, bb1);
        }
    }
    __syncthreads();   // last chunk's readers done before epilogue overwrites smem

    // ---- epilogue: diagonal extract d = sj - wp, coalesced float4 stores ----
    float* buf = reinterpret_cast<float*>(smem);   // [32][SAW] floats
#pragma unroll
    for (int chunk = 0; chunk < 3; chunk++) {
        const int d0 = chunk * 32;
        if (chunk) __syncthreads();
#pragma unroll
        for (int mt = 0; mt < 2; mt++) {
#pragma unroll
            for (int nt = 0; nt < 12; nt++) {
                const int ntg = nt + 2 * mt;
#pragma unroll
                for (int ci = 0; ci < 4; ci++) {
                    const int wp = w0 + 16 * mt + g + ((ci & 2) ? 8 : 0);
                    const int sj = w0 + 8 * ntg + 2 * l4 + (ci & 1);
                    const int d  = sj - wp;
                    if (d >= d0 && d < d0 + 32 && d < DD)
                        buf[(d - d0) * SAW + wp] = acc[mt][nt][ci] * (1.0f / 256.0f);
                }
            }
        }
        __syncthreads();
        const int dmax = (DD - d0 < 32) ? (DD - d0) : 32;
        for (int i = tid; i < dmax * 48; i += NTHR) {
            const int dd = i / 48;
            const int v  = i - dd * 48;
            *reinterpret_cast<float4*>(pout + (size_t)(d0 + dd) * HW + v * 4) =
                *reinterpret_cast<float4*>(&buf[dd * SAW + v * 4]);
        }
    }
}

extern "C" void kernel_launch(void* const* d_in, const int* in_sizes, int n_in,
                              void* d_out, int out_size) {
    const float* in1 = (const float*)d_in[0];
    const float* in2 = (const float*)d_in[1];
    float* out = (float*)d_out;

    cudaFuncSetAttribute(corr_hmma10, cudaFuncAttributeMaxDynamicSharedMemorySize, SMEM_BYTES);
    dim3 grid(HH, BB);   // 768 CTAs x 192 threads
    corr_hmma10<<<grid, NTHR, SMEM_BYTES>>>(in1, in2, out);
}